// round 1
// baseline (speedup 1.0000x reference)
#include <cuda_runtime.h>
#include <cstdint>
#include <math.h>

#define NN 1024
#define NP 16
#define NB 2048
#define SSZ 18433
#define NEU_OFF 1025
#define PEP_OFF 2049
#define DTc (1.0f/120.0f)

// ---------------------------------------------------------------------------
// Kernel 1: firing + peptide reaction-diffusion + partial neuron update.
// One block per batch row, 1024 threads (one per neuron).
// Peptide slab staged in SMEM transposed [p][n] (stride 1026 => conflict-free).
// ---------------------------------------------------------------------------
extern "C" __global__ void __launch_bounds__(1024)
k1_kernel(const float* __restrict__ u, const float* __restrict__ state,
          const float* __restrict__ noise_u, const float* __restrict__ D,
          const float* __restrict__ prodr, const float* __restrict__ decayr,
          const float* __restrict__ act, const float* __restrict__ ndec,
          const float* __restrict__ inl, float* __restrict__ out_f,
          float* __restrict__ snew)
{
    extern __shared__ float s[];            // 16 * 1026 floats
    __shared__ float sD[16], sP[16], sDe[16], sA[16];
    const int tid = threadIdx.x;
    const int b = blockIdx.x;
    if (tid < 16) {
        sD[tid]  = fabsf(D[tid]);
        sP[tid]  = fabsf(prodr[tid]);
        sDe[tid] = fabsf(decayr[tid]);
        sA[tid]  = act[tid];
    }
    const float* __restrict__ srow = state + (size_t)b * SSZ;
    float* __restrict__ drow = snew + (size_t)b * SSZ;

    // Stage peptide slab (coalesced scalar loads; row base is only 4B aligned)
    #pragma unroll
    for (int k = 0; k < 16; k++) {
        int g = tid + k * 1024;             // element index within slab: n*16+p
        float v = srow[PEP_OFF + g];
        s[(g & 15) * 1026 + (g >> 4)] = v;  // transposed [p][n]
    }

    // Neuron-level elementwise work (independent of SMEM)
    const int n = tid;
    float abl = srow[n];
    float neu = srow[NEU_OFF + n];
    float nz  = noise_u[(size_t)b * NN + n];
    float nm  = neu * abl;                        // masked neuron
    float f   = fmaxf(neu, 0.0f) * abl;
    f = -(f + 0.01f) * log1pf(-nz);
    f = fminf(fmaxf(f, 0.0f), 10.0f);
    out_f[(size_t)b * NN + n] = f;                // firing output (= GEMM A)
    drow[n] = abl;                                // ablate passthrough
    float pc2 = __ldg(srow + NN);
    if (tid == 0) drow[NN] = pc2;                 // pc2 passthrough
    float ub  = __ldg(u + b);
    float ndv = fabsf(__ldg(ndec));
    float il  = inl[n];

    __syncthreads();

    // Peptide: 5-point Laplacian on 32x32 torus (n = r*32 + c), per channel p
    const int r = n >> 5, c = n & 31;
    const int n_up = (((r + 1)  & 31) << 5) | c;
    const int n_dn = (((r + 31) & 31) << 5) | c;
    const int n_rt = (r << 5) | ((c + 1)  & 31);
    const int n_lf = (r << 5) | ((c + 31) & 31);

    float pnew[16];
    float psum = 0.0f;
    #pragma unroll
    for (int p = 0; p < 16; p++) {
        const float* sp = s + p * 1026;
        float ctr = sp[n];
        float lap = sp[n_up] + sp[n_dn] + sp[n_rt] + sp[n_lf] - 4.0f * ctr;
        float d   = sP[p] * f - sDe[p] * ctr + sD[p] * lap;
        pnew[p]   = ctr + d * DTc;
        psum     += ctr * sA[p];
    }
    // Partial neuron update (GEMM term added by kernel 2 epilogue)
    float dn_part = psum * pc2 - nm * ndv + il * ub;
    drow[NEU_OFF + n] = nm + dn_part * DTc;

    __syncthreads();                              // all Laplacian reads done
    #pragma unroll
    for (int p = 0; p < 16; p++) s[p * 1026 + n] = pnew[p];
    __syncthreads();

    // Coalesced write-back of new peptide slab
    #pragma unroll
    for (int k = 0; k < 16; k++) {
        int g = tid + k * 1024;
        drow[PEP_OFF + g] = s[(g & 15) * 1026 + (g >> 4)];
    }
}

// ---------------------------------------------------------------------------
// Kernel 2: C = firing @ synapse via tf32 mma.sync, fused epilogue:
//   state_new.neuron[m,n] = (tmp[m,n] + DT * C[m,n]) * ablate[m,n]
// Block tile 128x64, 8 warps (4m x 2n), warp tile 32x32, BK=16, double buffer.
// ---------------------------------------------------------------------------
#define BM 128
#define BN 64
#define BK 16
#define ASTR 136   // (8t+g) bank mapping -> conflict-free A fragment loads
#define BSTR 72

__device__ __forceinline__ uint32_t f2tf(float x) {
    uint32_t r;
    asm("cvt.rna.tf32.f32 %0, %1;" : "=r"(r) : "f"(x));
    return r;
}

__device__ __forceinline__ void mma8(float* c, const uint32_t* a, const uint32_t* b) {
    asm volatile(
        "mma.sync.aligned.m16n8k8.row.col.f32.tf32.tf32.f32 "
        "{%0,%1,%2,%3}, {%4,%5,%6,%7}, {%8,%9}, {%0,%1,%2,%3};"
        : "+f"(c[0]), "+f"(c[1]), "+f"(c[2]), "+f"(c[3])
        : "r"(a[0]), "r"(a[1]), "r"(a[2]), "r"(a[3]), "r"(b[0]), "r"(b[1]));
}

extern "C" __global__ void __launch_bounds__(256)
k2_gemm(const float* __restrict__ A,      // firing [2048,1024]
        const float* __restrict__ B,      // synapse [1024,1024]
        const float* __restrict__ state,  // original state (ablate)
        float* __restrict__ snew)
{
    __shared__ uint32_t As[2][BK * ASTR];
    __shared__ uint32_t Bs[2][BK * BSTR];

    const int tid  = threadIdx.x;
    const int lane = tid & 31;
    const int warp = tid >> 5;
    const int wm = warp >> 1, wn = warp & 1;
    const int g = lane >> 2, t = lane & 3;
    const int m0 = blockIdx.y * BM;
    const int n0 = blockIdx.x * BN;

    // Staging indices
    const int am = (tid >> 2);        // 0..63 (+64 on second pass)
    const int aq = (tid & 3);         // k-quad
    const int bk = (tid >> 4);        // 0..15
    const int bq = (tid & 3) + ((tid >> 4) & 0) * 0; // placeholder
    const int bn4 = (tid & 15);       // 0..15 -> 4-col group

    float acc[2][4][4];
    #pragma unroll
    for (int i = 0; i < 2; i++)
        #pragma unroll
        for (int j = 0; j < 4; j++)
            #pragma unroll
            for (int k = 0; k < 4; k++) acc[i][j][k] = 0.0f;

    // --- stage tile kt=0 into buffer 0 ---
    {
        #pragma unroll
        for (int it = 0; it < 2; it++) {
            int m = am + it * 64;
            float4 v = *(const float4*)(A + (size_t)(m0 + m) * 1024 + 4 * aq);
            As[0][(4 * aq + 0) * ASTR + m] = f2tf(v.x);
            As[0][(4 * aq + 1) * ASTR + m] = f2tf(v.y);
            As[0][(4 * aq + 2) * ASTR + m] = f2tf(v.z);
            As[0][(4 * aq + 3) * ASTR + m] = f2tf(v.w);
        }
        float4 v = *(const float4*)(B + (size_t)bk * 1024 + n0 + 4 * bn4);
        uint32_t* dst = &Bs[0][bk * BSTR + 4 * bn4];
        dst[0] = f2tf(v.x); dst[1] = f2tf(v.y); dst[2] = f2tf(v.z); dst[3] = f2tf(v.w);
    }
    __syncthreads();

    for (int kt = 0; kt < 1024 / BK; kt++) {
        const int cur = kt & 1, nxt = cur ^ 1;
        float4 pa0, pa1, pb;
        const bool has_next = (kt < 1024 / BK - 1);
        if (has_next) {
            int k0 = (kt + 1) * BK;
            pa0 = *(const float4*)(A + (size_t)(m0 + am)      * 1024 + k0 + 4 * aq);
            pa1 = *(const float4*)(A + (size_t)(m0 + am + 64) * 1024 + k0 + 4 * aq);
            pb  = *(const float4*)(B + (size_t)(k0 + bk) * 1024 + n0 + 4 * bn4);
        }

        #pragma unroll
        for (int s = 0; s < 2; s++) {
            const int kk = s * 8;
            uint32_t a[2][4], bf[4][2];
            #pragma unroll
            for (int sm = 0; sm < 2; sm++) {
                int mb = wm * 32 + sm * 16;
                a[sm][0] = As[cur][(kk + t)     * ASTR + mb + g];
                a[sm][1] = As[cur][(kk + t)     * ASTR + mb + g + 8];
                a[sm][2] = As[cur][(kk + t + 4) * ASTR + mb + g];
                a[sm][3] = As[cur][(kk + t + 4) * ASTR + mb + g + 8];
            }
            #pragma unroll
            for (int sn = 0; sn < 4; sn++) {
                int nb = wn * 32 + sn * 8;
                bf[sn][0] = Bs[cur][(kk + t)     * BSTR + nb + g];
                bf[sn][1] = Bs[cur][(kk + t + 4) * BSTR + nb + g];
            }
            #pragma unroll
            for (int sm = 0; sm < 2; sm++)
                #pragma unroll
                for (int sn = 0; sn < 4; sn++)
                    mma8(acc[sm][sn], a[sm], bf[sn]);
        }

        if (has_next) {
            As[nxt][(4 * aq + 0) * ASTR + am] = f2tf(pa0.x);
            As[nxt][(4 * aq + 1) * ASTR + am] = f2tf(pa0.y);
            As[nxt][(4 * aq + 2) * ASTR + am] = f2tf(pa0.z);
            As[nxt][(4 * aq + 3) * ASTR + am] = f2tf(pa0.w);
            As[nxt][(4 * aq + 0) * ASTR + am + 64] = f2tf(pa1.x);
            As[nxt][(4 * aq + 1) * ASTR + am + 64] = f2tf(pa1.y);
            As[nxt][(4 * aq + 2) * ASTR + am + 64] = f2tf(pa1.z);
            As[nxt][(4 * aq + 3) * ASTR + am + 64] = f2tf(pa1.w);
            uint32_t* dst = &Bs[nxt][bk * BSTR + 4 * bn4];
            dst[0] = f2tf(pb.x); dst[1] = f2tf(pb.y); dst[2] = f2tf(pb.z); dst[3] = f2tf(pb.w);
        }
        __syncthreads();
    }

    // Fused epilogue: RMW into state_new neuron slice
    #pragma unroll
    for (int sm = 0; sm < 2; sm++) {
        #pragma unroll
        for (int sn = 0; sn < 4; sn++) {
            int row0 = m0 + wm * 32 + sm * 16 + g;
            int col0 = n0 + wn * 32 + sn * 8 + 2 * t;
            #pragma unroll
            for (int h = 0; h < 2; h++) {
                int m = row0 + h * 8;
                size_t off = (size_t)m * SSZ;
                #pragma unroll
                for (int j = 0; j < 2; j++) {
                    int nn = col0 + j;
                    float cc  = acc[sm][sn][h * 2 + j];
                    float tmp = snew[off + NEU_OFF + nn];
                    float abl = state[off + nn];
                    snew[off + NEU_OFF + nn] = (tmp + DTc * cc) * abl;
                }
            }
        }
    }
}

// ---------------------------------------------------------------------------
extern "C" void kernel_launch(void* const* d_in, const int* in_sizes, int n_in,
                              void* d_out, int out_size) {
    const float* u      = (const float*)d_in[0];
    const float* state  = (const float*)d_in[1];
    const float* noise  = (const float*)d_in[2];
    const float* D      = (const float*)d_in[3];
    const float* prodr  = (const float*)d_in[4];
    const float* decayr = (const float*)d_in[5];
    const float* act    = (const float*)d_in[6];
    const float* syn    = (const float*)d_in[7];
    const float* ndec   = (const float*)d_in[8];
    const float* inl    = (const float*)d_in[9];

    float* out   = (float*)d_out;
    float* out_f = out;                         // firing [2048,1024]
    float* snew  = out + (size_t)NB * NN;       // state_new [2048,18433]

    const int smem1 = 16 * 1026 * sizeof(float);
    cudaFuncSetAttribute(k1_kernel, cudaFuncAttributeMaxDynamicSharedMemorySize, smem1);

    k1_kernel<<<NB, 1024, smem1>>>(u, state, noise, D, prodr, decayr, act,
                                   ndec, inl, out_f, snew);

    dim3 grid(NN / BN, NB / BM);
    k2_gemm<<<grid, 256>>>(out_f, syn, state, snew);
}

// round 2
// speedup vs baseline: 1.2980x; 1.2980x over previous
#include <cuda_runtime.h>
#include <cuda_bf16.h>
#include <cstdint>
#include <math.h>

#define NN 1024
#define NP 16
#define NB 2048
#define SSZ 18433
#define NEU_OFF 1025
#define PEP_OFF 2049
#define DTc (1.0f/120.0f)

// bf16 scratch operands for the GEMM (device globals: no allocations)
__device__ __nv_bfloat16 g_Abf[(size_t)NB * NN];   // firing, bf16
__device__ __nv_bfloat16 g_Bbf[(size_t)NN * NN];   // synapse, bf16

// ---------------------------------------------------------------------------
// Kernel 0: convert synapse fp32 -> bf16 (row-major preserved)
// ---------------------------------------------------------------------------
extern "C" __global__ void __launch_bounds__(256)
k0_conv(const float* __restrict__ B)
{
    int i = blockIdx.x * 256 + threadIdx.x;          // float4 index
    float4 v = ((const float4*)B)[i];
    __nv_bfloat162* dst = (__nv_bfloat162*)g_Bbf;
    dst[2 * i + 0] = __floats2bfloat162_rn(v.x, v.y);
    dst[2 * i + 1] = __floats2bfloat162_rn(v.z, v.w);
}

// ---------------------------------------------------------------------------
// Kernel 1: firing + peptide reaction-diffusion + partial neuron update.
// (unchanged from R1 except: also writes firing as bf16 to g_Abf)
// ---------------------------------------------------------------------------
extern "C" __global__ void __launch_bounds__(1024)
k1_kernel(const float* __restrict__ u, const float* __restrict__ state,
          const float* __restrict__ noise_u, const float* __restrict__ D,
          const float* __restrict__ prodr, const float* __restrict__ decayr,
          const float* __restrict__ act, const float* __restrict__ ndec,
          const float* __restrict__ inl, float* __restrict__ out_f,
          float* __restrict__ snew)
{
    extern __shared__ float s[];            // 16 * 1026 floats
    __shared__ float sD[16], sP[16], sDe[16], sA[16];
    const int tid = threadIdx.x;
    const int b = blockIdx.x;
    if (tid < 16) {
        sD[tid]  = fabsf(D[tid]);
        sP[tid]  = fabsf(prodr[tid]);
        sDe[tid] = fabsf(decayr[tid]);
        sA[tid]  = act[tid];
    }
    const float* __restrict__ srow = state + (size_t)b * SSZ;
    float* __restrict__ drow = snew + (size_t)b * SSZ;

    #pragma unroll
    for (int k = 0; k < 16; k++) {
        int g = tid + k * 1024;
        float v = srow[PEP_OFF + g];
        s[(g & 15) * 1026 + (g >> 4)] = v;
    }

    const int n = tid;
    float abl = srow[n];
    float neu = srow[NEU_OFF + n];
    float nz  = noise_u[(size_t)b * NN + n];
    float nm  = neu * abl;
    float f   = fmaxf(neu, 0.0f) * abl;
    f = -(f + 0.01f) * log1pf(-nz);
    f = fminf(fmaxf(f, 0.0f), 10.0f);
    out_f[(size_t)b * NN + n] = f;
    g_Abf[(size_t)b * NN + n] = __float2bfloat16_rn(f);
    drow[n] = abl;
    float pc2 = __ldg(srow + NN);
    if (tid == 0) drow[NN] = pc2;
    float ub  = __ldg(u + b);
    float ndv = fabsf(__ldg(ndec));
    float il  = inl[n];

    __syncthreads();

    const int r = n >> 5, c = n & 31;
    const int n_up = (((r + 1)  & 31) << 5) | c;
    const int n_dn = (((r + 31) & 31) << 5) | c;
    const int n_rt = (r << 5) | ((c + 1)  & 31);
    const int n_lf = (r << 5) | ((c + 31) & 31);

    float pnew[16];
    float psum = 0.0f;
    #pragma unroll
    for (int p = 0; p < 16; p++) {
        const float* sp = s + p * 1026;
        float ctr = sp[n];
        float lap = sp[n_up] + sp[n_dn] + sp[n_rt] + sp[n_lf] - 4.0f * ctr;
        float d   = sP[p] * f - sDe[p] * ctr + sD[p] * lap;
        pnew[p]   = ctr + d * DTc;
        psum     += ctr * sA[p];
    }
    float dn_part = psum * pc2 - nm * ndv + il * ub;
    drow[NEU_OFF + n] = nm + dn_part * DTc;

    __syncthreads();
    #pragma unroll
    for (int p = 0; p < 16; p++) s[p * 1026 + n] = pnew[p];
    __syncthreads();

    #pragma unroll
    for (int k = 0; k < 16; k++) {
        int g = tid + k * 1024;
        drow[PEP_OFF + g] = s[(g & 15) * 1026 + (g >> 4)];
    }
}

// ---------------------------------------------------------------------------
// Kernel 2: C = firing @ synapse in bf16 (m16n8k16 + ldmatrix + cp.async),
// fused epilogue: state_new.neuron = (tmp + DT*C) * ablate
// BM=128, BN=64, BK=64 halfs; 8 warps (4m x 2n), warp tile 32x32.
// Smem rows are 128B with XOR-8 16B-chunk swizzle: conflict-free everywhere.
// ---------------------------------------------------------------------------
#define BM 128
#define BN 64
#define BKH 64              // k-extent per tile in halfs (128 bytes)
#define KITERS (NN / BKH)   // 16

#define A_TILE_BYTES (BM * BKH * 2)   // 16384
#define B_TILE_BYTES (BKH * BN * 2)   // 8192
#define SMEM_K2 (2 * (A_TILE_BYTES + B_TILE_BYTES))  // 49152

__device__ __forceinline__ void cpa16(uint32_t s, const void* g) {
    asm volatile("cp.async.cg.shared.global [%0], [%1], 16;" :: "r"(s), "l"(g));
}
#define CP_COMMIT() asm volatile("cp.async.commit_group;")
#define CP_WAIT(n)  asm volatile("cp.async.wait_group %0;" :: "n"(n))

__device__ __forceinline__ void ldsm4(uint32_t& r0, uint32_t& r1, uint32_t& r2,
                                      uint32_t& r3, uint32_t a) {
    asm volatile("ldmatrix.sync.aligned.m8n8.x4.shared.b16 {%0,%1,%2,%3}, [%4];"
                 : "=r"(r0), "=r"(r1), "=r"(r2), "=r"(r3) : "r"(a));
}
__device__ __forceinline__ void ldsm4t(uint32_t& r0, uint32_t& r1, uint32_t& r2,
                                       uint32_t& r3, uint32_t a) {
    asm volatile("ldmatrix.sync.aligned.m8n8.x4.trans.shared.b16 {%0,%1,%2,%3}, [%4];"
                 : "=r"(r0), "=r"(r1), "=r"(r2), "=r"(r3) : "r"(a));
}
__device__ __forceinline__ void mma16(float* c, const uint32_t* a, const uint32_t* b) {
    asm volatile(
        "mma.sync.aligned.m16n8k16.row.col.f32.bf16.bf16.f32 "
        "{%0,%1,%2,%3}, {%4,%5,%6,%7}, {%8,%9}, {%0,%1,%2,%3};"
        : "+f"(c[0]), "+f"(c[1]), "+f"(c[2]), "+f"(c[3])
        : "r"(a[0]), "r"(a[1]), "r"(a[2]), "r"(a[3]), "r"(b[0]), "r"(b[1]));
}

// byte offset within a tile for (row, 16B-chunk c): swizzled
__device__ __forceinline__ uint32_t swz(int row, int c) {
    return (uint32_t)(row * 128 + ((c ^ (row & 7)) << 4));
}

extern "C" __global__ void __launch_bounds__(256)
k2_gemm(const float* __restrict__ state, float* __restrict__ snew)
{
    extern __shared__ __align__(16) unsigned char dsm[];
    const uint32_t sbase = (uint32_t)__cvta_generic_to_shared(dsm);
    const uint32_t sA = sbase;                      // [2][A_TILE_BYTES]
    const uint32_t sB = sbase + 2 * A_TILE_BYTES;   // [2][B_TILE_BYTES]

    const int tid  = threadIdx.x;
    const int lane = tid & 31;
    const int warp = tid >> 5;
    const int wm = warp >> 1, wn = warp & 1;
    const int l15 = lane & 15, l16 = lane >> 4;
    const int m0 = blockIdx.y * BM;
    const int n0 = blockIdx.x * BN;

    const __nv_bfloat16* __restrict__ gA = g_Abf;
    const __nv_bfloat16* __restrict__ gB = g_Bbf;

    const int sr = tid >> 3;     // 0..31
    const int sc = tid & 7;      // 16B chunk within 128B row

    float acc[2][4][4];
    #pragma unroll
    for (int i = 0; i < 2; i++)
        #pragma unroll
        for (int j = 0; j < 4; j++)
            #pragma unroll
            for (int k = 0; k < 4; k++) acc[i][j][k] = 0.0f;

    // ---- stage tile kt into buffer (kt&1) ----
    auto stage = [&](int kt) {
        const int buf = kt & 1;
        const int kh = kt * BKH;
        uint32_t aB = sA + buf * A_TILE_BYTES;
        #pragma unroll
        for (int i = 0; i < 4; i++) {
            int row = sr + i * 32;
            cpa16(aB + swz(row, sc), gA + (size_t)(m0 + row) * NN + kh + sc * 8);
        }
        uint32_t bB = sB + buf * B_TILE_BYTES;
        #pragma unroll
        for (int i = 0; i < 2; i++) {
            int row = sr + i * 32;
            cpa16(bB + swz(row, sc), gB + (size_t)(kh + row) * NN + n0 + sc * 8);
        }
    };

    stage(0);
    CP_COMMIT();

    for (int kt = 0; kt < KITERS; kt++) {
        const int cur = kt & 1;
        if (kt + 1 < KITERS) {
            stage(kt + 1);
            CP_COMMIT();
            CP_WAIT(1);
        } else {
            CP_WAIT(0);
        }
        __syncthreads();

        const uint32_t aB = sA + cur * A_TILE_BYTES;
        const uint32_t bB = sB + cur * B_TILE_BYTES;

        #pragma unroll
        for (int s = 0; s < 4; s++) {               // 4 k16 steps per BK=64
            uint32_t a[2][4];
            #pragma unroll
            for (int sm = 0; sm < 2; sm++) {
                int row = wm * 32 + sm * 16 + l15;
                int ch  = 2 * s + l16;
                ldsm4(a[sm][0], a[sm][1], a[sm][2], a[sm][3], aB + swz(row, ch));
            }
            uint32_t bq[2][4];
            #pragma unroll
            for (int nt = 0; nt < 2; nt++) {
                int row = 16 * s + l15;
                int ch  = wn * 4 + nt * 2 + l16;
                ldsm4t(bq[nt][0], bq[nt][1], bq[nt][2], bq[nt][3], bB + swz(row, ch));
            }
            #pragma unroll
            for (int sm = 0; sm < 2; sm++)
                #pragma unroll
                for (int j = 0; j < 4; j++) {
                    uint32_t bp[2] = { bq[j >> 1][(j & 1) * 2],
                                       bq[j >> 1][(j & 1) * 2 + 1] };
                    mma16(acc[sm][j], a[sm], bp);
                }
        }
        __syncthreads();
    }

    // ---- fused epilogue: RMW into state_new neuron slice ----
    const int g = lane >> 2, t = lane & 3;
    #pragma unroll
    for (int sm = 0; sm < 2; sm++) {
        #pragma unroll
        for (int j = 0; j < 4; j++) {
            int row0 = m0 + wm * 32 + sm * 16 + g;
            int col0 = n0 + wn * 32 + j * 8 + 2 * t;
            #pragma unroll
            for (int h = 0; h < 2; h++) {
                int m = row0 + h * 8;
                size_t off = (size_t)m * SSZ;
                #pragma unroll
                for (int q = 0; q < 2; q++) {
                    int nn = col0 + q;
                    float cc  = acc[sm][j][h * 2 + q];
                    float tmp = snew[off + NEU_OFF + nn];
                    float abl = state[off + nn];
                    snew[off + NEU_OFF + nn] = (tmp + DTc * cc) * abl;
                }
            }
        }
    }
}

// ---------------------------------------------------------------------------
extern "C" void kernel_launch(void* const* d_in, const int* in_sizes, int n_in,
                              void* d_out, int out_size) {
    const float* u      = (const float*)d_in[0];
    const float* state  = (const float*)d_in[1];
    const float* noise  = (const float*)d_in[2];
    const float* D      = (const float*)d_in[3];
    const float* prodr  = (const float*)d_in[4];
    const float* decayr = (const float*)d_in[5];
    const float* act    = (const float*)d_in[6];
    const float* syn    = (const float*)d_in[7];
    const float* ndec   = (const float*)d_in[8];
    const float* inl    = (const float*)d_in[9];

    float* out   = (float*)d_out;
    float* out_f = out;                         // firing [2048,1024]
    float* snew  = out + (size_t)NB * NN;       // state_new [2048,18433]

    // synapse fp32 -> bf16 (1M elems, 4 per thread)
    k0_conv<<<NN * NN / 4 / 256, 256>>>(syn);

    const int smem1 = 16 * 1026 * sizeof(float);
    cudaFuncSetAttribute(k1_kernel, cudaFuncAttributeMaxDynamicSharedMemorySize, smem1);
    k1_kernel<<<NB, 1024, smem1>>>(u, state, noise, D, prodr, decayr, act,
                                   ndec, inl, out_f, snew);

    cudaFuncSetAttribute(k2_gemm, cudaFuncAttributeMaxDynamicSharedMemorySize, SMEM_K2);
    dim3 grid(NN / BN, NB / BM);
    k2_gemm<<<grid, 256, SMEM_K2>>>(state, snew);
}

// round 3
// speedup vs baseline: 1.3145x; 1.0127x over previous
#include <cuda_runtime.h>
#include <cuda_bf16.h>
#include <cstdint>
#include <math.h>

#define NN 1024
#define NP 16
#define NB 2048
#define SSZ 18433
#define NEU_OFF 1025
#define PEP_OFF 2049
#define DTc (1.0f/120.0f)

// bf16 scratch operands for the GEMM (device globals: no allocations)
__device__ __nv_bfloat16 g_Abf[(size_t)NB * NN];   // firing, bf16
__device__ __nv_bfloat16 g_Bbf[(size_t)NN * NN];   // synapse, bf16

// ---------------------------------------------------------------------------
// Kernel 1: firing + peptide reaction-diffusion + partial neuron update,
// plus folded-in synapse fp32->bf16 conversion (blocks 0..1023).
// One block per batch row, 1024 threads (one per neuron).
// Peptide slab staged in SMEM transposed [p][n] (stride 1026 => conflict-free).
// Torus Laplacian: rt/lf neighbors via warp shuffle (warp==row r, lane==col c),
// up/dn from SMEM. ctr kept in registers.
// ---------------------------------------------------------------------------
extern "C" __global__ void __launch_bounds__(1024)
k1_kernel(const float* __restrict__ u, const float* __restrict__ state,
          const float* __restrict__ noise_u, const float* __restrict__ D,
          const float* __restrict__ prodr, const float* __restrict__ decayr,
          const float* __restrict__ act, const float* __restrict__ ndec,
          const float* __restrict__ inl, const float* __restrict__ syn,
          float* __restrict__ out_f, float* __restrict__ snew)
{
    extern __shared__ float s[];            // 16 * 1026 floats
    __shared__ float sD[16], sP[16], sDe[16], sA[16];
    const int tid = threadIdx.x;
    const int b = blockIdx.x;

    // Folded synapse conversion: one row per block for b < 1024.
    if (b < NN) {
        size_t i = (size_t)b * NN + tid;
        g_Bbf[i] = __float2bfloat16_rn(syn[i]);
    }

    if (tid < 16) {
        sD[tid]  = fabsf(D[tid]);
        sP[tid]  = fabsf(prodr[tid]);
        sDe[tid] = fabsf(decayr[tid]);
        sA[tid]  = act[tid];
    }
    const float* __restrict__ srow = state + (size_t)b * SSZ;
    float* __restrict__ drow = snew + (size_t)b * SSZ;

    // Stage peptide slab (coalesced scalar loads; row base is only 4B aligned)
    #pragma unroll
    for (int k = 0; k < 16; k++) {
        int g = tid + k * 1024;             // element index within slab: n*16+p
        float v = __ldcs(srow + PEP_OFF + g);
        s[(g & 15) * 1026 + (g >> 4)] = v;  // transposed [p][n]
    }

    // Neuron-level elementwise work (independent of SMEM)
    const int n = tid;
    const int lane = tid & 31;
    float abl = srow[n];
    float neu = srow[NEU_OFF + n];
    float nz  = noise_u[(size_t)b * NN + n];
    float nm  = neu * abl;                        // masked neuron
    float f   = fmaxf(neu, 0.0f) * abl;
    f = -(f + 0.01f) * log1pf(-nz);
    f = fminf(fmaxf(f, 0.0f), 10.0f);
    out_f[(size_t)b * NN + n] = f;                // firing output
    g_Abf[(size_t)b * NN + n] = __float2bfloat16_rn(f);  // GEMM A operand
    drow[n] = abl;                                // ablate passthrough
    float pc2 = __ldg(srow + NN);
    if (tid == 0) drow[NN] = pc2;                 // pc2 passthrough
    float ub  = __ldg(u + b);
    float ndv = fabsf(__ldg(ndec));
    float il  = inl[n];

    __syncthreads();

    // Torus neighbors: warp = row r, lane = col c; rt/lf in-warp via shuffle.
    const int r = n >> 5;
    const int n_up = (((r + 1)  & 31) << 5) | lane;
    const int n_dn = (((r + 31) & 31) << 5) | lane;
    const int lrt = (lane + 1)  & 31;
    const int llf = (lane + 31) & 31;

    float ctr[16];
    #pragma unroll
    for (int p = 0; p < 16; p++) ctr[p] = s[p * 1026 + n];

    float psum = 0.0f;
    #pragma unroll
    for (int p = 0; p < 16; p++) {
        const float* sp = s + p * 1026;
        float up = sp[n_up];
        float dn = sp[n_dn];
        float rt = __shfl_sync(0xffffffffu, ctr[p], lrt);
        float lf = __shfl_sync(0xffffffffu, ctr[p], llf);
        float lap = up + dn + rt + lf - 4.0f * ctr[p];
        psum += ctr[p] * sA[p];
        float d = sP[p] * f - sDe[p] * ctr[p] + sD[p] * lap;
        ctr[p] = fmaf(d, DTc, ctr[p]);            // ctr now holds pnew
    }
    // Partial neuron update (GEMM term added by kernel 2 epilogue)
    float dn_part = psum * pc2 - nm * ndv + il * ub;
    drow[NEU_OFF + n] = nm + dn_part * DTc;

    __syncthreads();                              // all Laplacian reads done
    #pragma unroll
    for (int p = 0; p < 16; p++) s[p * 1026 + n] = ctr[p];
    __syncthreads();

    // Coalesced streaming write-back of new peptide slab
    #pragma unroll
    for (int k = 0; k < 16; k++) {
        int g = tid + k * 1024;
        __stcs(drow + PEP_OFF + g, s[(g & 15) * 1026 + (g >> 4)]);
    }
}

// ---------------------------------------------------------------------------
// Kernel 2: C = firing @ synapse in bf16 (m16n8k16 + ldmatrix + cp.async),
// fused epilogue: state_new.neuron = (tmp + DT*C) * ablate
// BM=128, BN=64, BK=64 halfs; 8 warps (4m x 2n), warp tile 32x32.
// ---------------------------------------------------------------------------
#define BM 128
#define BN 64
#define BKH 64
#define KITERS (NN / BKH)

#define A_TILE_BYTES (BM * BKH * 2)
#define B_TILE_BYTES (BKH * BN * 2)
#define SMEM_K2 (2 * (A_TILE_BYTES + B_TILE_BYTES))

__device__ __forceinline__ void cpa16(uint32_t s, const void* g) {
    asm volatile("cp.async.cg.shared.global [%0], [%1], 16;" :: "r"(s), "l"(g));
}
#define CP_COMMIT() asm volatile("cp.async.commit_group;")
#define CP_WAIT(n)  asm volatile("cp.async.wait_group %0;" :: "n"(n))

__device__ __forceinline__ void ldsm4(uint32_t& r0, uint32_t& r1, uint32_t& r2,
                                      uint32_t& r3, uint32_t a) {
    asm volatile("ldmatrix.sync.aligned.m8n8.x4.shared.b16 {%0,%1,%2,%3}, [%4];"
                 : "=r"(r0), "=r"(r1), "=r"(r2), "=r"(r3) : "r"(a));
}
__device__ __forceinline__ void ldsm4t(uint32_t& r0, uint32_t& r1, uint32_t& r2,
                                       uint32_t& r3, uint32_t a) {
    asm volatile("ldmatrix.sync.aligned.m8n8.x4.trans.shared.b16 {%0,%1,%2,%3}, [%4];"
                 : "=r"(r0), "=r"(r1), "=r"(r2), "=r"(r3) : "r"(a));
}
__device__ __forceinline__ void mma16(float* c, const uint32_t* a, const uint32_t* b) {
    asm volatile(
        "mma.sync.aligned.m16n8k16.row.col.f32.bf16.bf16.f32 "
        "{%0,%1,%2,%3}, {%4,%5,%6,%7}, {%8,%9}, {%0,%1,%2,%3};"
        : "+f"(c[0]), "+f"(c[1]), "+f"(c[2]), "+f"(c[3])
        : "r"(a[0]), "r"(a[1]), "r"(a[2]), "r"(a[3]), "r"(b[0]), "r"(b[1]));
}

__device__ __forceinline__ uint32_t swz(int row, int c) {
    return (uint32_t)(row * 128 + ((c ^ (row & 7)) << 4));
}

extern "C" __global__ void __launch_bounds__(256)
k2_gemm(const float* __restrict__ state, float* __restrict__ snew)
{
    extern __shared__ __align__(16) unsigned char dsm[];
    const uint32_t sbase = (uint32_t)__cvta_generic_to_shared(dsm);
    const uint32_t sA = sbase;
    const uint32_t sB = sbase + 2 * A_TILE_BYTES;

    const int tid  = threadIdx.x;
    const int lane = tid & 31;
    const int warp = tid >> 5;
    const int wm = warp >> 1, wn = warp & 1;
    const int l15 = lane & 15, l16 = lane >> 4;
    const int m0 = blockIdx.y * BM;
    const int n0 = blockIdx.x * BN;

    const __nv_bfloat16* __restrict__ gA = g_Abf;
    const __nv_bfloat16* __restrict__ gB = g_Bbf;

    const int sr = tid >> 3;
    const int sc = tid & 7;

    float acc[2][4][4];
    #pragma unroll
    for (int i = 0; i < 2; i++)
        #pragma unroll
        for (int j = 0; j < 4; j++)
            #pragma unroll
            for (int k = 0; k < 4; k++) acc[i][j][k] = 0.0f;

    auto stage = [&](int kt) {
        const int buf = kt & 1;
        const int kh = kt * BKH;
        uint32_t aB = sA + buf * A_TILE_BYTES;
        #pragma unroll
        for (int i = 0; i < 4; i++) {
            int row = sr + i * 32;
            cpa16(aB + swz(row, sc), gA + (size_t)(m0 + row) * NN + kh + sc * 8);
        }
        uint32_t bB = sB + buf * B_TILE_BYTES;
        #pragma unroll
        for (int i = 0; i < 2; i++) {
            int row = sr + i * 32;
            cpa16(bB + swz(row, sc), gB + (size_t)(kh + row) * NN + n0 + sc * 8);
        }
    };

    stage(0);
    CP_COMMIT();

    for (int kt = 0; kt < KITERS; kt++) {
        const int cur = kt & 1;
        if (kt + 1 < KITERS) {
            stage(kt + 1);
            CP_COMMIT();
            CP_WAIT(1);
        } else {
            CP_WAIT(0);
        }
        __syncthreads();

        const uint32_t aB = sA + cur * A_TILE_BYTES;
        const uint32_t bB = sB + cur * B_TILE_BYTES;

        #pragma unroll
        for (int s = 0; s < 4; s++) {
            uint32_t a[2][4];
            #pragma unroll
            for (int sm = 0; sm < 2; sm++) {
                int row = wm * 32 + sm * 16 + l15;
                int ch  = 2 * s + l16;
                ldsm4(a[sm][0], a[sm][1], a[sm][2], a[sm][3], aB + swz(row, ch));
            }
            uint32_t bq[2][4];
            #pragma unroll
            for (int nt = 0; nt < 2; nt++) {
                int row = 16 * s + l15;
                int ch  = wn * 4 + nt * 2 + l16;
                ldsm4t(bq[nt][0], bq[nt][1], bq[nt][2], bq[nt][3], bB + swz(row, ch));
            }
            #pragma unroll
            for (int sm = 0; sm < 2; sm++)
                #pragma unroll
                for (int j = 0; j < 4; j++) {
                    uint32_t bp[2] = { bq[j >> 1][(j & 1) * 2],
                                       bq[j >> 1][(j & 1) * 2 + 1] };
                    mma16(acc[sm][j], a[sm], bp);
                }
        }
        __syncthreads();
    }

    const int g = lane >> 2, t = lane & 3;
    #pragma unroll
    for (int sm = 0; sm < 2; sm++) {
        #pragma unroll
        for (int j = 0; j < 4; j++) {
            int row0 = m0 + wm * 32 + sm * 16 + g;
            int col0 = n0 + wn * 32 + j * 8 + 2 * t;
            #pragma unroll
            for (int h = 0; h < 2; h++) {
                int m = row0 + h * 8;
                size_t off = (size_t)m * SSZ;
                #pragma unroll
                for (int q = 0; q < 2; q++) {
                    int nn = col0 + q;
                    float cc  = acc[sm][j][h * 2 + q];
                    float tmp = snew[off + NEU_OFF + nn];
                    float abl = state[off + nn];
                    snew[off + NEU_OFF + nn] = (tmp + DTc * cc) * abl;
                }
            }
        }
    }
}

// ---------------------------------------------------------------------------
extern "C" void kernel_launch(void* const* d_in, const int* in_sizes, int n_in,
                              void* d_out, int out_size) {
    const float* u      = (const float*)d_in[0];
    const float* state  = (const float*)d_in[1];
    const float* noise  = (const float*)d_in[2];
    const float* D      = (const float*)d_in[3];
    const float* prodr  = (const float*)d_in[4];
    const float* decayr = (const float*)d_in[5];
    const float* act    = (const float*)d_in[6];
    const float* syn    = (const float*)d_in[7];
    const float* ndec   = (const float*)d_in[8];
    const float* inl    = (const float*)d_in[9];

    float* out   = (float*)d_out;
    float* out_f = out;                         // firing [2048,1024]
    float* snew  = out + (size_t)NB * NN;       // state_new [2048,18433]

    const int smem1 = 16 * 1026 * sizeof(float);
    cudaFuncSetAttribute(k1_kernel, cudaFuncAttributeMaxDynamicSharedMemorySize, smem1);
    k1_kernel<<<NB, 1024, smem1>>>(u, state, noise, D, prodr, decayr, act,
                                   ndec, inl, syn, out_f, snew);

    cudaFuncSetAttribute(k2_gemm, cudaFuncAttributeMaxDynamicSharedMemorySize, SMEM_K2);
    dim3 grid(NN / BN, NB / BM);
    k2_gemm<<<grid, 256, SMEM_K2>>>(state, snew);
}

// round 6
// speedup vs baseline: 1.3182x; 1.0028x over previous
#include <cuda_runtime.h>
#include <cuda_bf16.h>
#include <cstdint>
#include <math.h>

#define NN 1024
#define NP 16
#define NB 2048
#define SSZ 18433
#define NEU_OFF 1025
#define PEP_OFF 2049
#define DTc (1.0f/120.0f)

// bf16 scratch operands for the GEMM (device globals: no allocations)
__device__ __nv_bfloat16 g_Abf[(size_t)NB * NN];   // firing, bf16
__device__ __nv_bfloat16 g_Bbf[(size_t)NN * NN];   // synapse, bf16

// ---------------------------------------------------------------------------
// Kernel 1 (identical to R3 known-good): firing + peptide reaction-diffusion
// + partial neuron update + folded synapse fp32->bf16 (blocks 0..1023).
// One block per batch row, 1024 threads. Peptide slab staged in SMEM
// transposed [p][n] (stride 1026). rt/lf neighbors via warp shuffle.
// ---------------------------------------------------------------------------
extern "C" __global__ void __launch_bounds__(1024)
k1_kernel(const float* __restrict__ u, const float* __restrict__ state,
          const float* __restrict__ noise_u, const float* __restrict__ D,
          const float* __restrict__ prodr, const float* __restrict__ decayr,
          const float* __restrict__ act, const float* __restrict__ ndec,
          const float* __restrict__ inl, const float* __restrict__ syn,
          float* __restrict__ out_f, float* __restrict__ snew)
{
    extern __shared__ float s[];            // 16 * 1026 floats
    __shared__ float sD[16], sP[16], sDe[16], sA[16];
    const int tid = threadIdx.x;
    const int b = blockIdx.x;

    // Folded synapse conversion: one row per block for b < 1024.
    if (b < NN) {
        size_t i = (size_t)b * NN + tid;
        g_Bbf[i] = __float2bfloat16_rn(syn[i]);
    }

    if (tid < 16) {
        sD[tid]  = fabsf(D[tid]);
        sP[tid]  = fabsf(prodr[tid]);
        sDe[tid] = fabsf(decayr[tid]);
        sA[tid]  = act[tid];
    }
    const float* __restrict__ srow = state + (size_t)b * SSZ;
    float* __restrict__ drow = snew + (size_t)b * SSZ;

    // Stage peptide slab (coalesced scalar loads; row base is only 4B aligned)
    #pragma unroll
    for (int k = 0; k < 16; k++) {
        int g = tid + k * 1024;             // element index within slab: n*16+p
        float v = __ldcs(srow + PEP_OFF + g);
        s[(g & 15) * 1026 + (g >> 4)] = v;  // transposed [p][n]
    }

    // Neuron-level elementwise work (independent of SMEM)
    const int n = tid;
    const int lane = tid & 31;
    float abl = srow[n];
    float neu = srow[NEU_OFF + n];
    float nz  = noise_u[(size_t)b * NN + n];
    float nm  = neu * abl;
    float f   = fmaxf(neu, 0.0f) * abl;
    f = -(f + 0.01f) * log1pf(-nz);
    f = fminf(fmaxf(f, 0.0f), 10.0f);
    out_f[(size_t)b * NN + n] = f;
    g_Abf[(size_t)b * NN + n] = __float2bfloat16_rn(f);
    drow[n] = abl;
    float pc2 = __ldg(srow + NN);
    if (tid == 0) drow[NN] = pc2;
    float ub  = __ldg(u + b);
    float ndv = fabsf(__ldg(ndec));
    float il  = inl[n];

    __syncthreads();

    // Torus neighbors: warp = row r, lane = col c; rt/lf in-warp via shuffle.
    const int r = n >> 5;
    const int n_up = (((r + 1)  & 31) << 5) | lane;
    const int n_dn = (((r + 31) & 31) << 5) | lane;
    const int lrt = (lane + 1)  & 31;
    const int llf = (lane + 31) & 31;

    float ctr[16];
    #pragma unroll
    for (int p = 0; p < 16; p++) ctr[p] = s[p * 1026 + n];

    float psum = 0.0f;
    #pragma unroll
    for (int p = 0; p < 16; p++) {
        const float* sp = s + p * 1026;
        float up = sp[n_up];
        float dn = sp[n_dn];
        float rt = __shfl_sync(0xffffffffu, ctr[p], lrt);
        float lf = __shfl_sync(0xffffffffu, ctr[p], llf);
        float lap = up + dn + rt + lf - 4.0f * ctr[p];
        psum += ctr[p] * sA[p];
        float d = sP[p] * f - sDe[p] * ctr[p] + sD[p] * lap;
        ctr[p] = fmaf(d, DTc, ctr[p]);            // ctr now holds pnew
    }
    // Partial neuron update (GEMM term added by kernel 2 epilogue)
    float dn_part = psum * pc2 - nm * ndv + il * ub;
    drow[NEU_OFF + n] = nm + dn_part * DTc;

    __syncthreads();                              // all Laplacian reads done
    #pragma unroll
    for (int p = 0; p < 16; p++) s[p * 1026 + n] = ctr[p];
    __syncthreads();

    // Coalesced streaming write-back of new peptide slab
    #pragma unroll
    for (int k = 0; k < 16; k++) {
        int g = tid + k * 1024;
        __stcs(drow + PEP_OFF + g, s[(g & 15) * 1026 + (g >> 4)]);
    }
}

// ---------------------------------------------------------------------------
// Kernel 2: C = firing @ synapse in bf16 (m16n8k16 + ldmatrix + cp.async),
// fused epilogue: state_new.neuron = (tmp + DT*C) * ablate
// BM=64, BN=64, BK=64 halfs; 128 threads (4 warps, 2m x 2n), warp tile 32x32.
// 3-stage cp.async pipeline, one __syncthreads per K-tile.
// ---------------------------------------------------------------------------
#define BM 64
#define BN 64
#define BKH 64
#define KITERS (NN / BKH)          // 16
#define STAGES 3

#define A_TILE_BYTES (BM * BKH * 2)   // 8192
#define B_TILE_BYTES (BKH * BN * 2)   // 8192
#define SMEM_K2 (STAGES * (A_TILE_BYTES + B_TILE_BYTES))  // 49152

__device__ __forceinline__ void cpa16(uint32_t s, const void* g) {
    asm volatile("cp.async.cg.shared.global [%0], [%1], 16;" :: "r"(s), "l"(g));
}
#define CP_COMMIT() asm volatile("cp.async.commit_group;")
#define CP_WAIT(n)  asm volatile("cp.async.wait_group %0;" :: "n"(n))

__device__ __forceinline__ void ldsm4(uint32_t& r0, uint32_t& r1, uint32_t& r2,
                                      uint32_t& r3, uint32_t a) {
    asm volatile("ldmatrix.sync.aligned.m8n8.x4.shared.b16 {%0,%1,%2,%3}, [%4];"
                 : "=r"(r0), "=r"(r1), "=r"(r2), "=r"(r3) : "r"(a));
}
__device__ __forceinline__ void ldsm4t(uint32_t& r0, uint32_t& r1, uint32_t& r2,
                                       uint32_t& r3, uint32_t a) {
    asm volatile("ldmatrix.sync.aligned.m8n8.x4.trans.shared.b16 {%0,%1,%2,%3}, [%4];"
                 : "=r"(r0), "=r"(r1), "=r"(r2), "=r"(r3) : "r"(a));
}
__device__ __forceinline__ void mma16(float* c, const uint32_t* a, const uint32_t* b) {
    asm volatile(
        "mma.sync.aligned.m16n8k16.row.col.f32.bf16.bf16.f32 "
        "{%0,%1,%2,%3}, {%4,%5,%6,%7}, {%8,%9}, {%0,%1,%2,%3};"
        : "+f"(c[0]), "+f"(c[1]), "+f"(c[2]), "+f"(c[3])
        : "r"(a[0]), "r"(a[1]), "r"(a[2]), "r"(a[3]), "r"(b[0]), "r"(b[1]));
}

__device__ __forceinline__ uint32_t swz(int row, int c) {
    return (uint32_t)(row * 128 + ((c ^ (row & 7)) << 4));
}

extern "C" __global__ void __launch_bounds__(128)
k2_gemm(const float* __restrict__ state, float* __restrict__ snew)
{
    extern __shared__ __align__(16) unsigned char dsm[];
    const uint32_t sbase = (uint32_t)__cvta_generic_to_shared(dsm);
    const uint32_t sA = sbase;                          // [STAGES][A_TILE_BYTES]
    const uint32_t sB = sbase + STAGES * A_TILE_BYTES;  // [STAGES][B_TILE_BYTES]

    const int tid  = threadIdx.x;
    const int lane = tid & 31;
    const int warp = tid >> 5;
    const int wm = warp >> 1, wn = warp & 1;
    const int l15 = lane & 15, l16 = lane >> 4;
    const int m0 = blockIdx.y * BM;
    const int n0 = blockIdx.x * BN;

    const __nv_bfloat16* __restrict__ gA = g_Abf;
    const __nv_bfloat16* __restrict__ gB = g_Bbf;

    const int sr = tid >> 3;     // 0..15
    const int sc = tid & 7;      // 16B chunk within 128B row

    float acc[2][4][4];
    #pragma unroll
    for (int i = 0; i < 2; i++)
        #pragma unroll
        for (int j = 0; j < 4; j++)
            #pragma unroll
            for (int k = 0; k < 4; k++) acc[i][j][k] = 0.0f;

    auto stage = [&](int kt) {
        const int buf = kt % STAGES;
        const int kh = kt * BKH;
        uint32_t aB = sA + buf * A_TILE_BYTES;
        #pragma unroll
        for (int i = 0; i < 4; i++) {
            int row = sr + i * 16;
            cpa16(aB + swz(row, sc), gA + (size_t)(m0 + row) * NN + kh + sc * 8);
        }
        uint32_t bB = sB + buf * B_TILE_BYTES;
        #pragma unroll
        for (int i = 0; i < 4; i++) {
            int row = sr + i * 16;
            cpa16(bB + swz(row, sc), gB + (size_t)(kh + row) * NN + n0 + sc * 8);
        }
    };

    stage(0); CP_COMMIT();
    stage(1); CP_COMMIT();

    for (int kt = 0; kt < KITERS; kt++) {
        if (kt == KITERS - 1) { CP_WAIT(0); } else { CP_WAIT(1); }
        __syncthreads();

        const int cur = kt % STAGES;
        const uint32_t aB = sA + cur * A_TILE_BYTES;
        const uint32_t bB = sB + cur * B_TILE_BYTES;

        #pragma unroll
        for (int s = 0; s < 4; s++) {               // 4 k16 steps per BK=64
            uint32_t a[2][4];
            #pragma unroll
            for (int sm = 0; sm < 2; sm++) {
                int row = wm * 32 + sm * 16 + l15;
                int ch  = 2 * s + l16;
                ldsm4(a[sm][0], a[sm][1], a[sm][2], a[sm][3], aB + swz(row, ch));
            }
            uint32_t bq[2][4];
            #pragma unroll
            for (int nt = 0; nt < 2; nt++) {
                int row = 16 * s + l15;
                int ch  = wn * 4 + nt * 2 + l16;
                ldsm4t(bq[nt][0], bq[nt][1], bq[nt][2], bq[nt][3], bB + swz(row, ch));
            }
            #pragma unroll
            for (int sm = 0; sm < 2; sm++)
                #pragma unroll
                for (int j = 0; j < 4; j++) {
                    uint32_t bp[2] = { bq[j >> 1][(j & 1) * 2],
                                       bq[j >> 1][(j & 1) * 2 + 1] };
                    mma16(acc[sm][j], a[sm], bp);
                }
        }

        if (kt + 2 < KITERS) { stage(kt + 2); CP_COMMIT(); }
    }

    // ---- fused epilogue: RMW into state_new neuron slice ----
    const int g = lane >> 2, t = lane & 3;
    #pragma unroll
    for (int sm = 0; sm < 2; sm++) {
        #pragma unroll
        for (int j = 0; j < 4; j++) {
            int row0 = m0 + wm * 32 + sm * 16 + g;
            int col0 = n0 + wn * 32 + j * 8 + 2 * t;
            #pragma unroll
            for (int h = 0; h < 2; h++) {
                int m = row0 + h * 8;
                size_t off = (size_t)m * SSZ;
                #pragma unroll
                for (int q = 0; q < 2; q++) {
                    int nn = col0 + q;
                    float cc  = acc[sm][j][h * 2 + q];
                    float tmp = snew[off + NEU_OFF + nn];
                    float abl = state[off + nn];
                    snew[off + NEU_OFF + nn] = (tmp + DTc * cc) * abl;
                }
            }
        }
    }
}

// ---------------------------------------------------------------------------
extern "C" void kernel_launch(void* const* d_in, const int* in_sizes, int n_in,
                              void* d_out, int out_size) {
    const float* u      = (const float*)d_in[0];
    const float* state  = (const float*)d_in[1];
    const float* noise  = (const float*)d_in[2];
    const float* D      = (const float*)d_in[3];
    const float* prodr  = (const float*)d_in[4];
    const float* decayr = (const float*)d_in[5];
    const float* act    = (const float*)d_in[6];
    const float* syn    = (const float*)d_in[7];
    const float* ndec   = (const float*)d_in[8];
    const float* inl    = (const float*)d_in[9];

    float* out   = (float*)d_out;
    float* out_f = out;                         // firing [2048,1024]
    float* snew  = out + (size_t)NB * NN;       // state_new [2048,18433]

    const int smem1 = 16 * 1026 * sizeof(float);
    cudaFuncSetAttribute(k1_kernel, cudaFuncAttributeMaxDynamicSharedMemorySize, smem1);
    k1_kernel<<<NB, 1024, smem1>>>(u, state, noise, D, prodr, decayr, act,
                                   ndec, inl, syn, out_f, snew);

    cudaFuncSetAttribute(k2_gemm, cudaFuncAttributeMaxDynamicSharedMemorySize, SMEM_K2);
    dim3 grid(NN / BN, NB / BM);
    k2_gemm<<<grid, 128, SMEM_K2>>>(state, snew);
}